// round 13
// baseline (speedup 1.0000x reference)
#include <cuda_runtime.h>

// Single fused kernel, zero FP64 at runtime.
// out[n][d] = (x[n]==0 ? 0 : W[x[n]][d]) + PE(n,d)
// Seed path: compile-time two-float w table + fp32 EFT + Cody-Waite + MUFU.
// Hot loop: G=8 batched gathers. L2 range policy: first 120MB of W (fits L2)
// -> evict_last (resident after first touch, ~58% of uniform gathers hit);
// rest of W -> evict_first (streams without evicting the resident window).
// Stores are evict-first streaming. fp32 rotation recurrence, exact reseed
// every 128 rows.

#define D_DIM   1024
#define TPB     256
#define ROWS    128
#define G       8

// ---- compile-time construction of w = r^k as two-float ----
constexpr double cexp_small(double x) {       // |x|<0.02: Taylor, full DP prec
    double t = 1.0, term = 1.0;
    for (int i = 1; i < 22; i++) { term *= x / (double)i; t += term; }
    return t;
}
constexpr double cpow_u(double base, int n) { // binary exponentiation
    double acc = 1.0, b = base;
    while (n) { if (n & 1) acc *= b; b *= b; n >>= 1; }
    return acc;
}
constexpr double R_STEP = cexp_small(-9.210340371976184 / 512.0); // 10000^{-1/512}

#define CW(k)  cpow_u(R_STEP, (k))
#define WHI(k) ((float)CW(k))
#define WLO(k) ((float)(CW(k) - (double)((float)CW(k))))
#define W2(k)  { WHI(k), WLO(k) }
#define W2R(b) W2(b+0),W2(b+1),W2(b+2),W2(b+3),W2(b+4),W2(b+5),W2(b+6),W2(b+7), \
               W2(b+8),W2(b+9),W2(b+10),W2(b+11),W2(b+12),W2(b+13),W2(b+14),W2(b+15), \
               W2(b+16),W2(b+17),W2(b+18),W2(b+19),W2(b+20),W2(b+21),W2(b+22),W2(b+23), \
               W2(b+24),W2(b+25),W2(b+26),W2(b+27),W2(b+28),W2(b+29),W2(b+30),W2(b+31)

__device__ const float2 g_w2[513] = {
    W2R(0),   W2R(32),  W2R(64),  W2R(96),  W2R(128), W2R(160), W2R(192), W2R(224),
    W2R(256), W2R(288), W2R(320), W2R(352), W2R(384), W2R(416), W2R(448), W2R(480),
    W2(512)
};

// gather load with range-based L2 policy descriptor
__device__ __forceinline__ float4 ldg_pol(const float4* p, unsigned long long pol) {
    float4 v;
    asm volatile("ld.global.nc.L2::cache_hint.v4.f32 {%0,%1,%2,%3}, [%4], %5;"
                 : "=f"(v.x), "=f"(v.y), "=f"(v.z), "=f"(v.w)
                 : "l"(p), "l"(pol));
    return v;
}

__global__ __launch_bounds__(TPB, 3)
void pe_embed_fused(const int* __restrict__ x,
                    const float* __restrict__ W,
                    float* __restrict__ out,
                    int N, unsigned int prim_bytes, unsigned int total_bytes)
{
    __shared__ int sx[ROWS];

    const int chunk = blockIdx.x;
    const int n0 = chunk * ROWS;
    const int t  = threadIdx.x;

    if (t < ROWS) {
        int n = n0 + t;
        sx[t] = (n < N) ? x[n] : 0;
    }

    // Range policy: W[0, prim) -> evict_last (L2-resident),
    //               W[prim, total) -> evict_first (streamed).
    unsigned long long pol;
    asm("createpolicy.range.global.L2::evict_last.L2::evict_first.b64 %0, [%1], %2, %3;"
        : "=l"(pol) : "l"(W), "r"(prim_bytes), "r"(total_bytes));

    // states m=0..2 use exponent e = 4t+2m -> table index ie = 2t+m
    float s[3], c[3], sw[3], cw[3];
    {
        const float INV_2PI = 0.15915494309189535f;
        const float C1 = 6.28125f;                 // 201/32: k*C1 exact for k<2^15
        const float C2 = 1.9353071795864770e-3f;   // 2pi - C1
        const float p  = (float)(n0 + 1);          // exact: < 2^17
#pragma unroll
        for (int m = 0; m < 3; m++) {
            int ie = 2 * t + m;
            float2 wv = __ldg(&g_w2[ie]);
            // two-float product p*w
            float hi  = p * wv.x;
            float err = fmaf(p, wv.x, -hi);        // exact residual
            float lo  = fmaf(p, wv.y, err);
            // Cody-Waite mod 2pi
            float k = rintf(hi * INV_2PI);
            float r = fmaf(-k, C1, hi);
            r = fmaf(-k, C2, r);
            r += lo;
            __sincosf(r, &s[m], &c[m]);
            // per-row rotation constants
            float w1 = wv.x + wv.y;
            __sincosf(w1, &sw[m], &cw[m]);
        }
    }
    __syncthreads();

    const float4* __restrict__ Wv = (const float4*)W;
    float4* outv = (float4*)out;

    const int nr = (N - n0 < ROWS) ? (N - n0) : ROWS;
    const long obase = (long)n0 * (D_DIM / 4) + t;

    if (nr == ROWS) {
        // fast path: batch G row-gathers before compute/store -> deep MLP
        for (int rb = 0; rb < ROWS; rb += G) {
            int    idx[G];
            float4 e[G];
#pragma unroll
            for (int j = 0; j < G; j++) idx[j] = sx[rb + j];
#pragma unroll
            for (int j = 0; j < G; j++)   // unconditional: row 0 is valid memory
                e[j] = ldg_pol(&Wv[(long)idx[j] * (D_DIM / 4) + t], pol);
#pragma unroll
            for (int j = 0; j < G; j++) {
                float msk = (idx[j] == 0) ? 0.f : 1.f;   // padding row -> zero
                float4 o;
                o.x = fmaf(e[j].x, msk, c[0]);
                o.y = fmaf(e[j].y, msk, s[1]);
                o.z = fmaf(e[j].z, msk, c[1]);
                o.w = fmaf(e[j].w, msk, s[2]);
                __stcs(&outv[obase + (long)(rb + j) * (D_DIM / 4)], o);
#pragma unroll
                for (int m = 0; m < 3; m++) {
                    float ns = fmaf(s[m], cw[m],  c[m] * sw[m]);
                    float nc = fmaf(c[m], cw[m], -s[m] * sw[m]);
                    s[m] = ns; c[m] = nc;
                }
            }
        }
    } else {
        for (int r = 0; r < nr; r++) {
            int idx = sx[r];
            float4 e = make_float4(0.f, 0.f, 0.f, 0.f);
            if (idx != 0) e = ldg_pol(&Wv[(long)idx * (D_DIM / 4) + t], pol);
            float4 o;
            o.x = e.x + c[0];
            o.y = e.y + s[1];
            o.z = e.z + c[1];
            o.w = e.w + s[2];
            __stcs(&outv[obase + (long)r * (D_DIM / 4)], o);
#pragma unroll
            for (int m = 0; m < 3; m++) {
                float ns = fmaf(s[m], cw[m],  c[m] * sw[m]);
                float nc = fmaf(c[m], cw[m], -s[m] * sw[m]);
                s[m] = ns; c[m] = nc;
            }
        }
    }
}

extern "C" void kernel_launch(void* const* d_in, const int* in_sizes, int n_in,
                              void* d_out, int out_size)
{
    const int*   x;
    const float* W;
    int N; long welems;
    if (in_sizes[0] < in_sizes[1]) {
        x = (const int*)d_in[0];  W = (const float*)d_in[1];
        N = in_sizes[0];  welems = in_sizes[1];
    } else {
        x = (const int*)d_in[1];  W = (const float*)d_in[0];
        N = in_sizes[1];  welems = in_sizes[0];
    }
    unsigned int total_bytes = (unsigned int)(welems * 4);           // ~206 MB
    unsigned int prim_bytes  = 120u * 1024u * 1024u;                 // 120 MB window
    if (prim_bytes > total_bytes) prim_bytes = total_bytes;

    int nchunks = (N + ROWS - 1) / ROWS;
    pe_embed_fused<<<nchunks, TPB>>>(x, W, (float*)d_out, N,
                                     prim_bytes, total_bytes);
}